// round 8
// baseline (speedup 1.0000x reference)
#include <cuda_runtime.h>
#include <cuda_fp16.h>
#include <cstdint>

// Problem constants
#define Bb 2
#define Cc 256
#define Hh 128
#define Ww 128
#define Oo 256
#define HW 16384            // H*W
#define DG 4
#define OFFC 72             // DG*9*2 offset channels
#define NCH 72              // chunks: (g*2+chalf)*9 + tap, K=32 each
#define WROW 40             // fp16 per W smem row (80B: 32 data + 8 pad)
#define WCHUNK (256 * WROW) // fp16 elems per W chunk (20480B)
#define WB2 20480           // W chunk bytes
#define SB2 5120            // S buffer bytes: 64 rows x 80B
#define XPW 129             // padded pair-row width
#define CSTR (Hh * XPW)     // half2 stride per channel

// Scratch (device globals: allocation-free rule)
__device__ float2 g_off2[Bb * 36 * HW];        // packed (dy,dx) per (b, g*9+tap, pixel)
__device__ __half g_wt[NCH * WCHUNK];          // fp16 weights, padded rows, per chunk
__device__ __half2 g_xp[Bb * Cc * CSTR];       // x as horizontal pairs (v[xi-1], v[xi]), fp16

// ---------------------------------------------------------------------------
// helpers
// ---------------------------------------------------------------------------
__device__ __forceinline__ uint32_t smem_u32(const void* p) {
    uint32_t a;
    asm("{ .reg .u64 t; cvta.to.shared.u64 t, %1; cvt.u32.u64 %0, t; }" : "=r"(a) : "l"(p));
    return a;
}
__device__ __forceinline__ void ldsm4(uint32_t* r, uint32_t addr) {
    asm volatile("ldmatrix.sync.aligned.m8n8.x4.shared.b16 {%0,%1,%2,%3}, [%4];"
                 : "=r"(r[0]), "=r"(r[1]), "=r"(r[2]), "=r"(r[3]) : "r"(addr));
}
__device__ __forceinline__ void mma_f16(float* c, const uint32_t* a, const uint32_t* b) {
    asm volatile(
        "mma.sync.aligned.m16n8k16.row.col.f32.f16.f16.f32 "
        "{%0,%1,%2,%3},{%4,%5,%6,%7},{%8,%9},{%0,%1,%2,%3};"
        : "+f"(c[0]), "+f"(c[1]), "+f"(c[2]), "+f"(c[3])
        : "r"(a[0]), "r"(a[1]), "r"(a[2]), "r"(a[3]), "r"(b[0]), "r"(b[1]));
}
__device__ __forceinline__ void sts128u(uint32_t a, uint32_t x, uint32_t y, uint32_t z, uint32_t w) {
    asm volatile("st.shared.v4.b32 [%0], {%1,%2,%3,%4};" :: "r"(a), "r"(x), "r"(y), "r"(z), "r"(w));
}
__device__ __forceinline__ void cp16(uint32_t dst, const void* src) {
    asm volatile("cp.async.cg.shared.global [%0], [%1], 16;" :: "r"(dst), "l"(src) : "memory");
}
__device__ __forceinline__ void cp_commit() {
    asm volatile("cp.async.commit_group;" ::: "memory");
}
template <int N>
__device__ __forceinline__ void cp_wait() {
    asm volatile("cp.async.wait_group %0;" :: "n"(N) : "memory");
}
// f32x2 packed-FMA helpers (K1)
__device__ __forceinline__ unsigned long long pack2(float v) {
    unsigned long long r;
    asm("mov.b64 %0, {%1, %1};" : "=l"(r) : "f"(v));
    return r;
}
__device__ __forceinline__ void fma2(unsigned long long& d, unsigned long long a,
                                     unsigned long long b) {
    asm("fma.rn.f32x2 %0, %1, %2, %0;" : "+l"(d) : "l"(a), "l"(b));
}
__device__ __forceinline__ void unpack2(unsigned long long r, float& lo, float& hi) {
    asm("mov.b64 {%0, %1}, %2;" : "=f"(lo), "=f"(hi) : "l"(r));
}

// ---------------------------------------------------------------------------
// K0a: transpose + fp16-round deform weights into padded per-chunk tiles.
// ---------------------------------------------------------------------------
__global__ void k_transpose_w(const float* __restrict__ w) {
    int idx = blockIdx.x * blockDim.x + threadIdx.x;
    if (idx >= Oo * Cc * 9) return;
    int o = idx / (Cc * 9);
    int r = idx % (Cc * 9);
    int c = r / 9;
    int tap = r % 9;
    int g = c >> 6;
    int chalf = (c >> 5) & 1;
    int cc = c & 31;
    int cid = (g * 2 + chalf) * 9 + tap;
    g_wt[(size_t)cid * WCHUNK + o * WROW + cc] = __float2half_rn(w[idx]);
}

// ---------------------------------------------------------------------------
// K0b: pack x into fp16 horizontal pairs with padded column.
// g_xp[(b*Cc+c)*CSTR + y*129 + xi] = ( v[xi-1], v[xi] ), v[-1]=v[128]=0.
// ---------------------------------------------------------------------------
__global__ void k_pack_x(const float* __restrict__ x) {
    int idx = blockIdx.x * blockDim.x + threadIdx.x;
    if (idx >= Bb * Cc * CSTR) return;
    int row = idx / XPW;          // (b*Cc+c)*Hh + y
    int xi = idx - row * XPW;
    const float* src = x + (size_t)row * Ww;
    float lo = (xi >= 1) ? __ldg(src + xi - 1) : 0.f;
    float hi = (xi <= 127) ? __ldg(src + xi) : 0.f;
    g_xp[idx] = __floats2half2_rn(lo, hi);
}

// ---------------------------------------------------------------------------
// K1: offset field = 1x1 conv (72x256 matvec per pixel) + bias. f32x2 FMAs.
// Writes packed float2 (dy,dx) planes: g_off2[b][g*9+tap][hw].
// ---------------------------------------------------------------------------
__global__ __launch_bounds__(256) void k_offset(const float* __restrict__ x,
                                                const float* __restrict__ w_off,
                                                const float* __restrict__ b_off) {
    extern __shared__ float ws[];  // [256][72], c-major
    for (int i = threadIdx.x; i < OFFC * Cc; i += blockDim.x) {
        int o = i / Cc, c = i % Cc;
        ws[c * OFFC + o] = w_off[i];
    }
    __syncthreads();

    int pix = blockIdx.x * 256 + threadIdx.x;   // 0..32767
    int b = pix >> 14;
    int hw = pix & (HW - 1);
    const float* xp = x + (size_t)b * Cc * HW + hw;

    unsigned long long acc2[36];
#pragma unroll
    for (int i = 0; i < 36; i++) acc2[i] = ((const unsigned long long*)b_off)[i];

    for (int c = 0; c < Cc; c++) {
        float v = __ldg(&xp[(size_t)c * HW]);
        unsigned long long vv = pack2(v);
        const float4* wrow = (const float4*)&ws[c * OFFC];
#pragma unroll
        for (int i = 0; i < 18; i++) {
            float4 w4 = wrow[i];
            unsigned long long w01, w23;
            asm("mov.b64 %0, {%1, %2};" : "=l"(w01) : "f"(w4.x), "f"(w4.y));
            asm("mov.b64 %0, {%1, %2};" : "=l"(w23) : "f"(w4.z), "f"(w4.w));
            fma2(acc2[i * 2], vv, w01);
            fma2(acc2[i * 2 + 1], vv, w23);
        }
    }
    float2* op = g_off2 + (size_t)b * 36 * HW + hw;
#pragma unroll
    for (int i = 0; i < 36; i++) {
        float lo, hi;
        unpack2(acc2[i], lo, hi);    // (dy, dx) of plane i = g*9+tap
        op[(size_t)i * HW] = make_float2(lo, hi);
    }
}

// ---------------------------------------------------------------------------
// K2: fused deformable conv + ReLU, fp16 mma.sync m16n8k16, fp32 accum.
// CTA = (b, row h, pixel half): 64 pixels x 256 outputs, 256 thr, 2 CTA/SM.
// Gathers use paired-fp16 rows: 2 LDG per (channel, sample) instead of 4.
// One barrier per chunk: cp_wait(W) -> sts S -> sync -> cp.async W' -> sample' -> gemm.
// ---------------------------------------------------------------------------
__global__ __launch_bounds__(256, 2) void k_deform(float* __restrict__ out) {
    extern __shared__ float dsm[];
    const uint32_t base = smem_u32(dsm);
    const uint32_t sWb[2] = {base, base + WB2};
    const uint32_t sSb[2] = {base + 2 * WB2, base + 2 * WB2 + SB2};

    const int bx = blockIdx.x;
    const int pseg = bx & 1;            // pixel half of the row
    const int h = (bx >> 1) & 127;
    const int b = bx >> 8;
    const int w0 = pseg * 64;
    const int tid = threadIdx.x;
    const int lid = tid & 31;
    const int wid = tid >> 5;
    const int wp = wid >> 2;       // p-half within tile (32p)
    const int wo = wid & 3;        // o-quarter (64o)

    // ldmatrix lane addressing
    const uint32_t a_row16 = lid & 15;
    const uint32_t a_csel = lid >> 4;
    const uint32_t b_row8 = (lid & 7) + ((lid >> 4) & 1) * 8;
    const uint32_t b_csel = (lid >> 3) & 1;

    float acc[2][8][4];
#pragma unroll
    for (int i = 0; i < 2; i++)
#pragma unroll
        for (int j = 0; j < 8; j++)
#pragma unroll
            for (int k = 0; k < 4; k++) acc[i][j][k] = 0.f;

    const int sp = tid & 63;       // this thread's pixel within the 64-tile
    const int cq = tid >> 6;       // 0..3: which 8 channels of the 32-chunk
    const int wpix = w0 + sp;      // image column

    // --- sampler for chunk cid -> 4 packed half2 (8 channels) ---
    auto sample = [&](int cid, uint32_t* v4) {
        const int gc = cid / 9;          // g*2+chalf
        const int tap = cid - gc * 9;
        const int g = gc >> 1;
        const float2 od = __ldg(&g_off2[((size_t)b * 36 + g * 9 + tap) * HW + h * Ww + wpix]);
        float ys = (float)(h - 1 + tap / 3) + od.x;
        float xs = (float)(wpix - 1 + tap % 3) + od.y;
        float y0f = floorf(ys), x0f = floorf(xs);
        float ly = ys - y0f, lx = xs - x0f;
        int y0 = (int)y0f;
        int xi = (int)x0f + 1;

        float wy0 = (y0 >= 0 && y0 < Hh) ? (1.f - ly) : 0.f;
        float wy1 = (y0 >= -1 && y0 < Hh - 1) ? ly : 0.f;
        bool okx = (xi >= 0 && xi <= Ww);
        float wl = okx ? (1.f - lx) : 0.f;
        float wh = okx ? lx : 0.f;
        int y0c = min(max(y0, 0), Hh - 1);
        int y1c = min(max(y0 + 1, 0), Hh - 1);
        int xic = min(max(xi, 0), Ww);

        const __half2* xb = g_xp + (size_t)(b * Cc + gc * 32 + cq * 8) * CSTR;
        const __half2* p0 = xb + (y0c * XPW + xic);
        const __half2* p1 = xb + (y1c * XPW + xic);

#pragma unroll
        for (int jj = 0; jj < 4; ++jj) {
            float s[2];
#pragma unroll
            for (int e = 0; e < 2; ++e) {
                int c = jj * 2 + e;
                float2 a = __half22float2(__ldg(p0 + (size_t)c * CSTR));
                float2 bb = __half22float2(__ldg(p1 + (size_t)c * CSTR));
                s[e] = (a.x * wl + a.y * wh) * wy0 + (bb.x * wl + bb.y * wh) * wy1;
            }
            __half2 hh = __floats2half2_rn(s[0], s[1]);
            v4[jj] = *(uint32_t*)&hh;
        }
    };

    // --- prologue: prefetch W(0), sample(0) ---
    {
        const char* wsrc = (const char*)(g_wt);
        for (int i = tid; i < WB2 / 16; i += 256)
            cp16(sWb[0] + (uint32_t)i * 16u, wsrc + i * 16);
        cp_commit();
    }
    uint32_t v4[4];
    sample(0, v4);

    const uint32_t s_addr_base = (uint32_t)(sp * 80 + cq * 16);

    for (int t = 0; t < NCH; ++t) {
        const int buf = t & 1;

        cp_wait<0>();   // this thread's W(t) copies done
        sts128u(sSb[buf] + s_addr_base, v4[0], v4[1], v4[2], v4[3]);
        __syncthreads();  // all sts + all threads' W(t) copies complete

        if (t + 1 < NCH) {
            const char* wsrc = (const char*)(g_wt + (size_t)(t + 1) * WCHUNK);
            const uint32_t wdst = sWb[(t + 1) & 1];
            for (int i = tid; i < WB2 / 16; i += 256)
                cp16(wdst + (uint32_t)i * 16u, wsrc + i * 16);
            cp_commit();
            sample(t + 1, v4);   // LDG latency hides under gemm(t)
        }

        // --- GEMM: acc[32p x 64o per warp] += S * W^T over 32 c ---
#pragma unroll
        for (int ks = 0; ks < 2; ++ks) {
            uint32_t afr[2][4];
#pragma unroll
            for (int mi = 0; mi < 2; ++mi) {
                uint32_t row = (uint32_t)(wp * 32 + mi * 16) + a_row16;
                ldsm4(afr[mi], sSb[buf] + row * 80u + ((uint32_t)(ks * 2) + a_csel) * 16u);
            }
            uint32_t bfr[4][4];
#pragma unroll
            for (int pi = 0; pi < 4; ++pi) {
                uint32_t row = (uint32_t)(wo * 64 + pi * 16) + b_row8;
                ldsm4(bfr[pi], sWb[buf] + row * 80u + ((uint32_t)(ks * 2) + b_csel) * 16u);
            }
#pragma unroll
            for (int mi = 0; mi < 2; ++mi)
#pragma unroll
                for (int ni = 0; ni < 8; ++ni)
                    mma_f16(acc[mi][ni], afr[mi], &bfr[ni >> 1][(ni & 1) * 2]);
        }
    }

    // --- epilogue: ReLU + store ---
    {
        const int gq = lid >> 2;   // 0..7 (p within 16-tile)
        const int tq = lid & 3;    // 0..3 (o pairs)
#pragma unroll
        for (int mi = 0; mi < 2; ++mi) {
#pragma unroll
            for (int ni = 0; ni < 8; ++ni) {
                int o = wo * 64 + ni * 8 + 2 * tq;
                int p = w0 + wp * 32 + mi * 16 + gq;
                float* op = out + ((size_t)(b * Oo + o)) * HW + h * Ww + p;
                op[0] = fmaxf(acc[mi][ni][0], 0.f);
                op[HW] = fmaxf(acc[mi][ni][1], 0.f);
                op[8] = fmaxf(acc[mi][ni][2], 0.f);
                op[HW + 8] = fmaxf(acc[mi][ni][3], 0.f);
            }
        }
    }
}

// ---------------------------------------------------------------------------
extern "C" void kernel_launch(void* const* d_in, const int* in_sizes, int n_in,
                              void* d_out, int out_size) {
    const float* x = (const float*)d_in[0];        // [2,256,128,128]
    const float* w_off = (const float*)d_in[1];    // [72,256,1,1]
    const float* b_off = (const float*)d_in[2];    // [72]
    const float* w_def = (const float*)d_in[3];    // [256,256,3,3]
    float* out = (float*)d_out;

    const int OFF_SMEM = OFFC * Cc * sizeof(float);   // 73728
    const int DEF_SMEM = 2 * WB2 + 2 * SB2;           // 51200

    cudaFuncSetAttribute(k_offset, cudaFuncAttributeMaxDynamicSharedMemorySize, OFF_SMEM);
    cudaFuncSetAttribute(k_deform, cudaFuncAttributeMaxDynamicSharedMemorySize, DEF_SMEM);

    k_transpose_w<<<(Oo * Cc * 9 + 255) / 256, 256>>>(w_def);
    k_pack_x<<<(Bb * Cc * CSTR + 255) / 256, 256>>>(x);
    k_offset<<<(Bb * HW) / 256, 256, OFF_SMEM>>>(x, w_off, b_off);
    k_deform<<<Bb * Hh * 2, 256, DEF_SMEM>>>(out);
}

// round 9
// speedup vs baseline: 1.1228x; 1.1228x over previous
#include <cuda_runtime.h>
#include <cuda_fp16.h>
#include <cstdint>

// Problem constants
#define Bb 2
#define Cc 256
#define Hh 128
#define Ww 128
#define Oo 256
#define HW 16384            // H*W
#define OFFC 72
#define NCH 36              // chunks: g*9 + tap, K=64 each
#define WCHUNK (256 * 64)   // fp16 elems per W chunk (32768B), XOR-swizzled rows
#define WB2 32768           // W chunk bytes
#define SROW 144            // S row stride bytes (64c*2B data + 16B pad)
#define SB2 (64 * SROW)     // S buffer bytes (9216)
#define XPW 129             // padded pair-row width
#define CSTR (Hh * XPW)     // half2 stride per channel

// Scratch (device globals: allocation-free rule)
__device__ float2 g_off2[Bb * 36 * HW];        // packed (dy,dx) per (b, g*9+tap, pixel)
__device__ __half g_wt[NCH * WCHUNK];          // fp16 weights, XOR-swizzled 128B rows
__device__ __half2 g_xp[Bb * Cc * CSTR];       // x as horizontal pairs (v[xi-1], v[xi]), fp16

// ---------------------------------------------------------------------------
// helpers
// ---------------------------------------------------------------------------
__device__ __forceinline__ uint32_t smem_u32(const void* p) {
    uint32_t a;
    asm("{ .reg .u64 t; cvta.to.shared.u64 t, %1; cvt.u32.u64 %0, t; }" : "=r"(a) : "l"(p));
    return a;
}
__device__ __forceinline__ void ldsm4(uint32_t* r, uint32_t addr) {
    asm volatile("ldmatrix.sync.aligned.m8n8.x4.shared.b16 {%0,%1,%2,%3}, [%4];"
                 : "=r"(r[0]), "=r"(r[1]), "=r"(r[2]), "=r"(r[3]) : "r"(addr));
}
__device__ __forceinline__ void mma_f16(float* c, const uint32_t* a, const uint32_t* b) {
    asm volatile(
        "mma.sync.aligned.m16n8k16.row.col.f32.f16.f16.f32 "
        "{%0,%1,%2,%3},{%4,%5,%6,%7},{%8,%9},{%0,%1,%2,%3};"
        : "+f"(c[0]), "+f"(c[1]), "+f"(c[2]), "+f"(c[3])
        : "r"(a[0]), "r"(a[1]), "r"(a[2]), "r"(a[3]), "r"(b[0]), "r"(b[1]));
}
__device__ __forceinline__ void sts128u(uint32_t a, uint32_t x, uint32_t y, uint32_t z, uint32_t w) {
    asm volatile("st.shared.v4.b32 [%0], {%1,%2,%3,%4};" :: "r"(a), "r"(x), "r"(y), "r"(z), "r"(w));
}
__device__ __forceinline__ void cp16(uint32_t dst, const void* src) {
    asm volatile("cp.async.cg.shared.global [%0], [%1], 16;" :: "r"(dst), "l"(src) : "memory");
}
__device__ __forceinline__ void cp_commit() {
    asm volatile("cp.async.commit_group;" ::: "memory");
}
template <int N>
__device__ __forceinline__ void cp_wait() {
    asm volatile("cp.async.wait_group %0;" :: "n"(N) : "memory");
}
// f32x2 packed-FMA helpers (K1)
__device__ __forceinline__ void fma2(unsigned long long& d, unsigned long long a,
                                     unsigned long long b) {
    asm("fma.rn.f32x2 %0, %1, %2, %0;" : "+l"(d) : "l"(a), "l"(b));
}
__device__ __forceinline__ void unpack2(unsigned long long r, float& lo, float& hi) {
    asm("mov.b64 {%0, %1}, %2;" : "=f"(lo), "=f"(hi) : "l"(r));
}

// ---------------------------------------------------------------------------
// K0a: transpose + fp16-round + XOR-swizzle deform weights.
// [O][C][3][3] -> g_wt[cid=g*9+tap][o][64c], 128B rows, 16B unit XOR (cc>>2)^(o&7)
// ---------------------------------------------------------------------------
__global__ void k_transpose_w(const float* __restrict__ w) {
    int idx = blockIdx.x * blockDim.x + threadIdx.x;
    if (idx >= Oo * Cc * 9) return;
    int o = idx / (Cc * 9);
    int r = idx % (Cc * 9);
    int c = r / 9;
    int tap = r % 9;
    int g = c >> 6;
    int cc = c & 63;
    int cid = g * 9 + tap;
    int unit = (cc >> 3) ^ (o & 7);      // 16B unit (8 fp16) within the 128B row
    g_wt[(size_t)cid * WCHUNK + o * 64 + unit * 8 + (cc & 7)] = __float2half_rn(w[idx]);
}

// ---------------------------------------------------------------------------
// K0b: pack x into fp16 horizontal pairs with padded column.
// ---------------------------------------------------------------------------
__global__ void k_pack_x(const float* __restrict__ x) {
    int idx = blockIdx.x * blockDim.x + threadIdx.x;
    if (idx >= Bb * Cc * CSTR) return;
    int row = idx / XPW;          // (b*Cc+c)*Hh + y
    int xi = idx - row * XPW;
    const float* src = x + (size_t)row * Ww;
    float lo = (xi >= 1) ? __ldg(src + xi - 1) : 0.f;
    float hi = (xi <= 127) ? __ldg(src + xi) : 0.f;
    g_xp[idx] = __floats2half2_rn(lo, hi);
}

// ---------------------------------------------------------------------------
// K1: offset field. 2 pixels/thread + o-split(2): a 2-thread team shares
// weight LDS across 2 pixels; each thread computes 36 of the 72 outputs.
// Block = 256 threads -> 256 pixels.
// ---------------------------------------------------------------------------
__global__ __launch_bounds__(256) void k_offset(const float* __restrict__ x,
                                                const float* __restrict__ w_off,
                                                const float* __restrict__ b_off) {
    extern __shared__ float ws[];  // [256][72], c-major
    for (int i = threadIdx.x; i < OFFC * Cc; i += blockDim.x) {
        int o = i / Cc, c = i % Cc;
        ws[c * OFFC + o] = w_off[i];
    }
    __syncthreads();

    const int team = threadIdx.x >> 1;       // 0..127 -> pixel pair
    const int oh = threadIdx.x & 1;          // o-half (36 outputs)
    int pix0 = blockIdx.x * 256 + team * 2;  // first pixel of the pair
    int b = pix0 >> 14;
    int hw = pix0 & (HW - 1);
    const float* xp = x + (size_t)b * Cc * HW + hw;

    // acc[px][i]: 18 u64 per pixel (36 fp32 offsets)
    unsigned long long acc[2][18];
#pragma unroll
    for (int i = 0; i < 18; i++) {
        unsigned long long bb = ((const unsigned long long*)b_off)[oh * 18 + i];
        acc[0][i] = bb;
        acc[1][i] = bb;
    }

    for (int c = 0; c < Cc; c++) {
        float2 v = __ldg((const float2*)&xp[(size_t)c * HW]);
        unsigned long long v0, v1;
        asm("mov.b64 %0, {%1, %1};" : "=l"(v0) : "f"(v.x));
        asm("mov.b64 %0, {%1, %1};" : "=l"(v1) : "f"(v.y));
        const float4* wrow = (const float4*)&ws[c * OFFC + oh * 36];
#pragma unroll
        for (int i = 0; i < 9; i++) {
            float4 w4 = wrow[i];
            unsigned long long w01, w23;
            asm("mov.b64 %0, {%1, %2};" : "=l"(w01) : "f"(w4.x), "f"(w4.y));
            asm("mov.b64 %0, {%1, %2};" : "=l"(w23) : "f"(w4.z), "f"(w4.w));
            fma2(acc[0][i * 2], v0, w01);
            fma2(acc[0][i * 2 + 1], v0, w23);
            fma2(acc[1][i * 2], v1, w01);
            fma2(acc[1][i * 2 + 1], v1, w23);
        }
    }
    // outputs: oh half covers planes/components [oh*36, oh*36+36) of the 72
    // channel layout: ch = i2*2 + comp, plane = ch>>1... directly: channel index
    // q = oh*36 + j (j=0..35); q even -> dy of plane q/2, odd -> dx.
#pragma unroll
    for (int px = 0; px < 2; ++px) {
        float* op = (float*)(g_off2 + (size_t)b * 36 * HW) ;
#pragma unroll
        for (int i = 0; i < 18; i++) {
            float lo, hi;
            unpack2(acc[px][i], lo, hi);
            int q0 = oh * 36 + i * 2;
            // g_off2 plane p stores (dy,dx) interleaved: float index = (p*HW + hw)*2 + comp
            int p0 = q0 >> 1;
            op[((size_t)p0 * HW + hw + px) * 2 + (q0 & 1)] = lo;
            int q1 = q0 + 1;
            int p1 = q1 >> 1;
            op[((size_t)p1 * HW + hw + px) * 2 + (q1 & 1)] = hi;
        }
    }
}

// ---------------------------------------------------------------------------
// K2: fused deformable conv + ReLU, fp16 mma.sync m16n8k16, fp32 accum.
// CTA = (b,h,pixel-half): 64p x 256o, 256 thr, 2 CTA/SM. 36 K-chunks of 64c
// (one (g,tap) each): one offset/coord computation feeds 16 channels/thread.
// One barrier per chunk. S: 144B-stride padded rows; W: XOR-swizzled 128B rows.
// ---------------------------------------------------------------------------
__global__ __launch_bounds__(256, 2) void k_deform(float* __restrict__ out) {
    extern __shared__ float dsm[];
    const uint32_t base = smem_u32(dsm);
    const uint32_t sWb[2] = {base, base + WB2};
    const uint32_t sSb[2] = {base + 2 * WB2, base + 2 * WB2 + SB2};

    const int bx = blockIdx.x;
    const int pseg = bx & 1;
    const int h = (bx >> 1) & 127;
    const int b = bx >> 8;
    const int w0 = pseg * 64;
    const int tid = threadIdx.x;
    const int lid = tid & 31;
    const int wid = tid >> 5;
    const int wp = wid >> 2;       // p-half within tile (32p)
    const int wo = wid & 3;        // o-quarter (64o)

    // ldmatrix lane addressing
    const uint32_t a_row16 = lid & 15;
    const uint32_t a_csel = lid >> 4;
    const uint32_t b_row8 = (lid & 7) + ((lid >> 4) & 1) * 8;
    const uint32_t b_csel = (lid >> 3) & 1;

    float acc[2][8][4];
#pragma unroll
    for (int i = 0; i < 2; i++)
#pragma unroll
        for (int j = 0; j < 8; j++)
#pragma unroll
            for (int k = 0; k < 4; k++) acc[i][j][k] = 0.f;

    const int sp = tid & 63;       // this thread's pixel within the 64-tile
    const int cq = tid >> 6;       // 0..3: which 16 channels of the 64-chunk
    const int wpix = w0 + sp;      // image column

    // --- sampler for chunk cid -> 8 packed half2 (16 channels) ---
    auto sample = [&](int cid, uint32_t* v8) {
        const int g = cid / 9;
        const int tap = cid - g * 9;
        const float2 od = __ldg(&g_off2[((size_t)b * 36 + cid) * HW + h * Ww + wpix]);
        float ys = (float)(h - 1 + tap / 3) + od.x;
        float xs = (float)(wpix - 1 + tap % 3) + od.y;
        float y0f = floorf(ys), x0f = floorf(xs);
        float ly = ys - y0f, lx = xs - x0f;
        int y0 = (int)y0f;
        int xi = (int)x0f + 1;

        float wy0 = (y0 >= 0 && y0 < Hh) ? (1.f - ly) : 0.f;
        float wy1 = (y0 >= -1 && y0 < Hh - 1) ? ly : 0.f;
        bool okx = (xi >= 0 && xi <= Ww);
        float wl = okx ? (1.f - lx) : 0.f;
        float wh = okx ? lx : 0.f;
        int y0c = min(max(y0, 0), Hh - 1);
        int y1c = min(max(y0 + 1, 0), Hh - 1);
        int xic = min(max(xi, 0), Ww);

        const __half2* xb = g_xp + (size_t)(b * Cc + g * 64 + cq * 16) * CSTR;
        const __half2* p0 = xb + (y0c * XPW + xic);
        const __half2* p1 = xb + (y1c * XPW + xic);

#pragma unroll
        for (int jj = 0; jj < 8; ++jj) {
            float s[2];
#pragma unroll
            for (int e = 0; e < 2; ++e) {
                int c = jj * 2 + e;
                float2 a = __half22float2(__ldg(p0 + (size_t)c * CSTR));
                float2 bb = __half22float2(__ldg(p1 + (size_t)c * CSTR));
                s[e] = (a.x * wl + a.y * wh) * wy0 + (bb.x * wl + bb.y * wh) * wy1;
            }
            __half2 hh = __floats2half2_rn(s[0], s[1]);
            v8[jj] = *(uint32_t*)&hh;
        }
    };

    // --- prologue: prefetch W(0), sample(0) ---
    {
        const char* wsrc = (const char*)(g_wt);
        for (int i = tid; i < WB2 / 16; i += 256)
            cp16(sWb[0] + (uint32_t)i * 16u, wsrc + i * 16);
        cp_commit();
    }
    uint32_t v8[8];
    sample(0, v8);

    const uint32_t s_addr = (uint32_t)(sp * SROW + cq * 32);

    for (int t = 0; t < NCH; ++t) {
        const int buf = t & 1;

        cp_wait<0>();   // W(t) landed
        sts128u(sSb[buf] + s_addr, v8[0], v8[1], v8[2], v8[3]);
        sts128u(sSb[buf] + s_addr + 16u, v8[4], v8[5], v8[6], v8[7]);
        __syncthreads();  // all sts + all threads' W(t) copies complete

        if (t + 1 < NCH) {
            const char* wsrc = (const char*)(g_wt + (size_t)(t + 1) * WCHUNK);
            const uint32_t wdst = sWb[(t + 1) & 1];
            for (int i = tid; i < WB2 / 16; i += 256)
                cp16(wdst + (uint32_t)i * 16u, wsrc + i * 16);
            cp_commit();
            sample(t + 1, v8);   // LDG latency hides under gemm(t)
        }

        // --- GEMM: acc[32p x 64o per warp] += S * W^T over 64 c ---
#pragma unroll
        for (int ks = 0; ks < 4; ++ks) {
            uint32_t afr[2][4];
#pragma unroll
            for (int mi = 0; mi < 2; ++mi) {
                uint32_t row = (uint32_t)(wp * 32 + mi * 16) + a_row16;
                ldsm4(afr[mi], sSb[buf] + row * SROW + ((uint32_t)(ks * 2) + a_csel) * 16u);
            }
            uint32_t bfr[4][4];
#pragma unroll
            for (int pi = 0; pi < 4; ++pi) {
                uint32_t row = (uint32_t)(wo * 64 + pi * 16) + b_row8;
                uint32_t unit = ((uint32_t)(ks * 2) + b_csel) ^ (row & 7);
                ldsm4(bfr[pi], sWb[buf] + row * 128u + unit * 16u);
            }
#pragma unroll
            for (int mi = 0; mi < 2; ++mi)
#pragma unroll
                for (int ni = 0; ni < 8; ++ni)
                    mma_f16(acc[mi][ni], afr[mi], &bfr[ni >> 1][(ni & 1) * 2]);
        }
    }

    // --- epilogue: ReLU + store ---
    {
        const int gq = lid >> 2;   // 0..7 (p within 16-tile)
        const int tq = lid & 3;    // 0..3 (o pairs)
#pragma unroll
        for (int mi = 0; mi < 2; ++mi) {
#pragma unroll
            for (int ni = 0; ni < 8; ++ni) {
                int o = wo * 64 + ni * 8 + 2 * tq;
                int p = w0 + wp * 32 + mi * 16 + gq;
                float* op = out + ((size_t)(b * Oo + o)) * HW + h * Ww + p;
                op[0] = fmaxf(acc[mi][ni][0], 0.f);
                op[HW] = fmaxf(acc[mi][ni][1], 0.f);
                op[8] = fmaxf(acc[mi][ni][2], 0.f);
                op[HW + 8] = fmaxf(acc[mi][ni][3], 0.f);
            }
        }
    }
}

// ---------------------------------------------------------------------------
extern "C" void kernel_launch(void* const* d_in, const int* in_sizes, int n_in,
                              void* d_out, int out_size) {
    const float* x = (const float*)d_in[0];        // [2,256,128,128]
    const float* w_off = (const float*)d_in[1];    // [72,256,1,1]
    const float* b_off = (const float*)d_in[2];    // [72]
    const float* w_def = (const float*)d_in[3];    // [256,256,3,3]
    float* out = (float*)d_out;

    const int OFF_SMEM = OFFC * Cc * sizeof(float);   // 73728
    const int DEF_SMEM = 2 * WB2 + 2 * SB2;           // 83968

    cudaFuncSetAttribute(k_offset, cudaFuncAttributeMaxDynamicSharedMemorySize, OFF_SMEM);
    cudaFuncSetAttribute(k_deform, cudaFuncAttributeMaxDynamicSharedMemorySize, DEF_SMEM);

    k_transpose_w<<<(Oo * Cc * 9 + 255) / 256, 256>>>(w_def);
    k_pack_x<<<(Bb * Cc * CSTR + 255) / 256, 256>>>(x);
    k_offset<<<(Bb * HW) / 256, 256, OFF_SMEM>>>(x, w_off, b_off);
    k_deform<<<Bb * Hh * 2, 256, DEF_SMEM>>>(out);
}

// round 10
// speedup vs baseline: 1.2286x; 1.0943x over previous
#include <cuda_runtime.h>
#include <cuda_fp16.h>
#include <cstdint>

// Problem constants
#define Bb 2
#define Cc 256
#define Hh 128
#define Ww 128
#define Oo 256
#define HW 16384            // H*W
#define OFFC 72
#define NCH 36              // chunks: g*9 + tap, K=64 each
#define WCHUNK (256 * 64)   // fp16 elems per W chunk (32768B), XOR-swizzled rows
#define WB2 32768           // W chunk bytes
#define SROW 144            // S row stride bytes (64c*2B data + 16B pad)
#define SB2 (64 * SROW)     // S buffer bytes (9216)
#define XPW 129             // padded pair-row width
#define NQ 64               // channel quads per batch image

// Scratch (device globals: allocation-free rule)
__device__ float2 g_off2[Bb * 36 * HW];          // packed (dy,dx) per (b, g*9+tap, pixel)
__device__ __half g_wt[NCH * WCHUNK];            // fp16 weights, XOR-swizzled 128B rows
__device__ uint4 g_xq[Bb * NQ * Hh * XPW];       // 4-channel quad of horizontal pairs per (y,xi)

// ---------------------------------------------------------------------------
// helpers
// ---------------------------------------------------------------------------
__device__ __forceinline__ uint32_t smem_u32(const void* p) {
    uint32_t a;
    asm("{ .reg .u64 t; cvta.to.shared.u64 t, %1; cvt.u32.u64 %0, t; }" : "=r"(a) : "l"(p));
    return a;
}
__device__ __forceinline__ void ldsm4(uint32_t* r, uint32_t addr) {
    asm volatile("ldmatrix.sync.aligned.m8n8.x4.shared.b16 {%0,%1,%2,%3}, [%4];"
                 : "=r"(r[0]), "=r"(r[1]), "=r"(r[2]), "=r"(r[3]) : "r"(addr));
}
__device__ __forceinline__ void mma_f16(float* c, const uint32_t* a, const uint32_t* b) {
    asm volatile(
        "mma.sync.aligned.m16n8k16.row.col.f32.f16.f16.f32 "
        "{%0,%1,%2,%3},{%4,%5,%6,%7},{%8,%9},{%0,%1,%2,%3};"
        : "+f"(c[0]), "+f"(c[1]), "+f"(c[2]), "+f"(c[3])
        : "r"(a[0]), "r"(a[1]), "r"(a[2]), "r"(a[3]), "r"(b[0]), "r"(b[1]));
}
__device__ __forceinline__ void sts128u(uint32_t a, uint32_t x, uint32_t y, uint32_t z, uint32_t w) {
    asm volatile("st.shared.v4.b32 [%0], {%1,%2,%3,%4};" :: "r"(a), "r"(x), "r"(y), "r"(z), "r"(w));
}
__device__ __forceinline__ void cp16(uint32_t dst, const void* src) {
    asm volatile("cp.async.cg.shared.global [%0], [%1], 16;" :: "r"(dst), "l"(src) : "memory");
}
__device__ __forceinline__ void cp_commit() {
    asm volatile("cp.async.commit_group;" ::: "memory");
}
template <int N>
__device__ __forceinline__ void cp_wait() {
    asm volatile("cp.async.wait_group %0;" :: "n"(N) : "memory");
}
// f32x2 packed-FMA helpers (K1)
__device__ __forceinline__ void fma2(unsigned long long& d, unsigned long long a,
                                     unsigned long long b) {
    asm("fma.rn.f32x2 %0, %1, %2, %0;" : "+l"(d) : "l"(a), "l"(b));
}
__device__ __forceinline__ void unpack2(unsigned long long r, float& lo, float& hi) {
    asm("mov.b64 {%0, %1}, %2;" : "=f"(lo), "=f"(hi) : "l"(r));
}

// ---------------------------------------------------------------------------
// K0a: transpose + fp16-round + XOR-swizzle deform weights.
// [O][C][3][3] -> g_wt[cid=g*9+tap][o][64c], 128B rows, 16B-unit XOR (cc>>3)^(o&7)
// ---------------------------------------------------------------------------
__global__ void k_transpose_w(const float* __restrict__ w) {
    int idx = blockIdx.x * blockDim.x + threadIdx.x;
    if (idx >= Oo * Cc * 9) return;
    int o = idx / (Cc * 9);
    int r = idx % (Cc * 9);
    int c = r / 9;
    int tap = r % 9;
    int g = c >> 6;
    int cc = c & 63;
    int cid = g * 9 + tap;
    int unit = (cc >> 3) ^ (o & 7);
    g_wt[(size_t)cid * WCHUNK + o * 64 + unit * 8 + (cc & 7)] = __float2half_rn(w[idx]);
}

// ---------------------------------------------------------------------------
// K0b: pack x into 4-channel quads of fp16 horizontal pairs.
// g_xq[((b*NQ+q)*Hh + y)*XPW + xi] = { half2(v_c[xi-1], v_c[xi]) : c = q*4..q*4+3 }
// ---------------------------------------------------------------------------
__global__ void k_pack_q(const float* __restrict__ x) {
    int idx = blockIdx.x * blockDim.x + threadIdx.x;
    if (idx >= Bb * NQ * Hh * XPW) return;
    int xi = idx % XPW;
    int rest = idx / XPW;         // (b*NQ+q)*Hh + y
    int y = rest & 127;
    int bq = rest >> 7;
    int q = bq & (NQ - 1);
    int b = bq >> 6;
    const float* src = x + ((size_t)(b * Cc + q * 4) * Hh + y) * Ww;
    uint32_t u[4];
#pragma unroll
    for (int j = 0; j < 4; ++j) {
        const float* s = src + (size_t)j * HW;
        float lo = (xi >= 1) ? __ldg(s + xi - 1) : 0.f;
        float hi = (xi <= 127) ? __ldg(s + xi) : 0.f;
        __half2 hh = __floats2half2_rn(lo, hi);
        u[j] = *(uint32_t*)&hh;
    }
    g_xq[idx] = make_uint4(u[0], u[1], u[2], u[3]);
}

// ---------------------------------------------------------------------------
// K1: offset field. 2 pixels/thread-team + o-split(2). (R9 winner, unchanged)
// ---------------------------------------------------------------------------
__global__ __launch_bounds__(256) void k_offset(const float* __restrict__ x,
                                                const float* __restrict__ w_off,
                                                const float* __restrict__ b_off) {
    extern __shared__ float ws[];  // [256][72], c-major
    for (int i = threadIdx.x; i < OFFC * Cc; i += blockDim.x) {
        int o = i / Cc, c = i % Cc;
        ws[c * OFFC + o] = w_off[i];
    }
    __syncthreads();

    const int team = threadIdx.x >> 1;
    const int oh = threadIdx.x & 1;
    int pix0 = blockIdx.x * 256 + team * 2;
    int b = pix0 >> 14;
    int hw = pix0 & (HW - 1);
    const float* xp = x + (size_t)b * Cc * HW + hw;

    unsigned long long acc[2][18];
#pragma unroll
    for (int i = 0; i < 18; i++) {
        unsigned long long bb = ((const unsigned long long*)b_off)[oh * 18 + i];
        acc[0][i] = bb;
        acc[1][i] = bb;
    }

    for (int c = 0; c < Cc; c++) {
        float2 v = __ldg((const float2*)&xp[(size_t)c * HW]);
        unsigned long long v0, v1;
        asm("mov.b64 %0, {%1, %1};" : "=l"(v0) : "f"(v.x));
        asm("mov.b64 %0, {%1, %1};" : "=l"(v1) : "f"(v.y));
        const float4* wrow = (const float4*)&ws[c * OFFC + oh * 36];
#pragma unroll
        for (int i = 0; i < 9; i++) {
            float4 w4 = wrow[i];
            unsigned long long w01, w23;
            asm("mov.b64 %0, {%1, %2};" : "=l"(w01) : "f"(w4.x), "f"(w4.y));
            asm("mov.b64 %0, {%1, %2};" : "=l"(w23) : "f"(w4.z), "f"(w4.w));
            fma2(acc[0][i * 2], v0, w01);
            fma2(acc[0][i * 2 + 1], v0, w23);
            fma2(acc[1][i * 2], v1, w01);
            fma2(acc[1][i * 2 + 1], v1, w23);
        }
    }
#pragma unroll
    for (int px = 0; px < 2; ++px) {
        float* op = (float*)(g_off2 + (size_t)b * 36 * HW);
#pragma unroll
        for (int i = 0; i < 18; i++) {
            float lo, hi;
            unpack2(acc[px][i], lo, hi);
            int q0 = oh * 36 + i * 2;
            int p0 = q0 >> 1;
            op[((size_t)p0 * HW + hw + px) * 2 + (q0 & 1)] = lo;
            int q1 = q0 + 1;
            int p1 = q1 >> 1;
            op[((size_t)p1 * HW + hw + px) * 2 + (q1 & 1)] = hi;
        }
    }
}

// ---------------------------------------------------------------------------
// K2: fused deformable conv + ReLU, fp16 mma.sync m16n8k16, fp32 accum.
// CTA = (b,h,pixel-half): 64p x 256o, 256 thr, 2 CTA/SM. 36 K-chunks of 64c.
// Gathers: quad-packed 16B loads — 8 LDG.128 + 1 LDG.64 per thread per chunk.
// ---------------------------------------------------------------------------
__global__ __launch_bounds__(256, 2) void k_deform(float* __restrict__ out) {
    extern __shared__ float dsm[];
    const uint32_t base = smem_u32(dsm);
    const uint32_t sWb[2] = {base, base + WB2};
    const uint32_t sSb[2] = {base + 2 * WB2, base + 2 * WB2 + SB2};

    const int bx = blockIdx.x;
    const int pseg = bx & 1;
    const int h = (bx >> 1) & 127;
    const int b = bx >> 8;
    const int w0 = pseg * 64;
    const int tid = threadIdx.x;
    const int lid = tid & 31;
    const int wid = tid >> 5;
    const int wp = wid >> 2;       // p-half within tile (32p)
    const int wo = wid & 3;        // o-quarter (64o)

    // ldmatrix lane addressing
    const uint32_t a_row16 = lid & 15;
    const uint32_t a_csel = lid >> 4;
    const uint32_t b_row8 = (lid & 7) + ((lid >> 4) & 1) * 8;
    const uint32_t b_csel = (lid >> 3) & 1;

    float acc[2][8][4];
#pragma unroll
    for (int i = 0; i < 2; i++)
#pragma unroll
        for (int j = 0; j < 8; j++)
#pragma unroll
            for (int k = 0; k < 4; k++) acc[i][j][k] = 0.f;

    const int sp = tid & 63;       // this thread's pixel within the 64-tile
    const int cq = tid >> 6;       // 0..3: which 16 channels of the 64-chunk
    const int wpix = w0 + sp;      // image column

    // --- sampler for chunk cid -> 8 packed half2 (16 channels, quad loads) ---
    auto sample = [&](int cid, uint32_t* v8) {
        const int g = cid / 9;
        const int tap = cid - g * 9;
        const float2 od = __ldg(&g_off2[((size_t)b * 36 + cid) * HW + h * Ww + wpix]);
        float ys = (float)(h - 1 + tap / 3) + od.x;
        float xs = (float)(wpix - 1 + tap % 3) + od.y;
        float y0f = floorf(ys), x0f = floorf(xs);
        float ly = ys - y0f, lx = xs - x0f;
        int y0 = (int)y0f;
        int xi = (int)x0f + 1;

        float wy0 = (y0 >= 0 && y0 < Hh) ? (1.f - ly) : 0.f;
        float wy1 = (y0 >= -1 && y0 < Hh - 1) ? ly : 0.f;
        bool okx = (xi >= 0 && xi <= Ww);
        float wl = okx ? (1.f - lx) : 0.f;
        float wh = okx ? lx : 0.f;
        int y0c = min(max(y0, 0), Hh - 1);
        int y1c = min(max(y0 + 1, 0), Hh - 1);
        int xic = min(max(xi, 0), Ww);

        const int qbase = (b * NQ + g * 16 + cq * 4);
#pragma unroll
        for (int jj = 0; jj < 4; ++jj) {
            const uint4* rowb = g_xq + (size_t)(qbase + jj) * (Hh * XPW);
            uint4 l0 = __ldg(rowb + y0c * XPW + xic);
            uint4 l1 = __ldg(rowb + y1c * XPW + xic);
            float s[4];
            const uint32_t* u0 = (const uint32_t*)&l0;
            const uint32_t* u1 = (const uint32_t*)&l1;
#pragma unroll
            for (int j = 0; j < 4; ++j) {
                float2 a = __half22float2(*(const __half2*)&u0[j]);
                float2 bb = __half22float2(*(const __half2*)&u1[j]);
                s[j] = (a.x * wl + a.y * wh) * wy0 + (bb.x * wl + bb.y * wh) * wy1;
            }
            __half2 h0 = __floats2half2_rn(s[0], s[1]);
            __half2 h1 = __floats2half2_rn(s[2], s[3]);
            v8[jj * 2] = *(uint32_t*)&h0;
            v8[jj * 2 + 1] = *(uint32_t*)&h1;
        }
    };

    // --- prologue: prefetch W(0), sample(0) ---
    {
        const char* wsrc = (const char*)(g_wt);
        for (int i = tid; i < WB2 / 16; i += 256)
            cp16(sWb[0] + (uint32_t)i * 16u, wsrc + i * 16);
        cp_commit();
    }
    uint32_t v8[8];
    sample(0, v8);

    const uint32_t s_addr = (uint32_t)(sp * SROW + cq * 32);

    for (int t = 0; t < NCH; ++t) {
        const int buf = t & 1;

        cp_wait<0>();   // W(t) landed
        sts128u(sSb[buf] + s_addr, v8[0], v8[1], v8[2], v8[3]);
        sts128u(sSb[buf] + s_addr + 16u, v8[4], v8[5], v8[6], v8[7]);
        __syncthreads();  // all sts + all threads' W(t) copies complete

        if (t + 1 < NCH) {
            const char* wsrc = (const char*)(g_wt + (size_t)(t + 1) * WCHUNK);
            const uint32_t wdst = sWb[(t + 1) & 1];
            for (int i = tid; i < WB2 / 16; i += 256)
                cp16(wdst + (uint32_t)i * 16u, wsrc + i * 16);
            cp_commit();
            sample(t + 1, v8);   // LDG latency hides under gemm(t)
        }

        // --- GEMM: acc[32p x 64o per warp] += S * W^T over 64 c ---
#pragma unroll
        for (int ks = 0; ks < 4; ++ks) {
            uint32_t afr[2][4];
#pragma unroll
            for (int mi = 0; mi < 2; ++mi) {
                uint32_t row = (uint32_t)(wp * 32 + mi * 16) + a_row16;
                ldsm4(afr[mi], sSb[buf] + row * SROW + ((uint32_t)(ks * 2) + a_csel) * 16u);
            }
            uint32_t bfr[4][4];
#pragma unroll
            for (int pi = 0; pi < 4; ++pi) {
                uint32_t row = (uint32_t)(wo * 64 + pi * 16) + b_row8;
                uint32_t unit = ((uint32_t)(ks * 2) + b_csel) ^ (row & 7);
                ldsm4(bfr[pi], sWb[buf] + row * 128u + unit * 16u);
            }
#pragma unroll
            for (int mi = 0; mi < 2; ++mi)
#pragma unroll
                for (int ni = 0; ni < 8; ++ni)
                    mma_f16(acc[mi][ni], afr[mi], &bfr[ni >> 1][(ni & 1) * 2]);
        }
    }

    // --- epilogue: ReLU + store ---
    {
        const int gq = lid >> 2;   // 0..7 (p within 16-tile)
        const int tq = lid & 3;    // 0..3 (o pairs)
#pragma unroll
        for (int mi = 0; mi < 2; ++mi) {
#pragma unroll
            for (int ni = 0; ni < 8; ++ni) {
                int o = wo * 64 + ni * 8 + 2 * tq;
                int p = w0 + wp * 32 + mi * 16 + gq;
                float* op = out + ((size_t)(b * Oo + o)) * HW + h * Ww + p;
                op[0] = fmaxf(acc[mi][ni][0], 0.f);
                op[HW] = fmaxf(acc[mi][ni][1], 0.f);
                op[8] = fmaxf(acc[mi][ni][2], 0.f);
                op[HW + 8] = fmaxf(acc[mi][ni][3], 0.f);
            }
        }
    }
}

// ---------------------------------------------------------------------------
extern "C" void kernel_launch(void* const* d_in, const int* in_sizes, int n_in,
                              void* d_out, int out_size) {
    const float* x = (const float*)d_in[0];        // [2,256,128,128]
    const float* w_off = (const float*)d_in[1];    // [72,256,1,1]
    const float* b_off = (const float*)d_in[2];    // [72]
    const float* w_def = (const float*)d_in[3];    // [256,256,3,3]
    float* out = (float*)d_out;

    const int OFF_SMEM = OFFC * Cc * sizeof(float);   // 73728
    const int DEF_SMEM = 2 * WB2 + 2 * SB2;           // 83968

    cudaFuncSetAttribute(k_offset, cudaFuncAttributeMaxDynamicSharedMemorySize, OFF_SMEM);
    cudaFuncSetAttribute(k_deform, cudaFuncAttributeMaxDynamicSharedMemorySize, DEF_SMEM);

    k_transpose_w<<<(Oo * Cc * 9 + 255) / 256, 256>>>(w_def);
    k_pack_q<<<(Bb * NQ * Hh * XPW + 255) / 256, 256>>>(x);
    k_offset<<<(Bb * HW) / 256, 256, OFF_SMEM>>>(x, w_off, b_off);
    k_deform<<<Bb * Hh * 2, 256, DEF_SMEM>>>(out);
}

// round 11
// speedup vs baseline: 1.2385x; 1.0081x over previous
#include <cuda_runtime.h>
#include <cuda_fp16.h>
#include <cstdint>

// Problem constants
#define Bb 2
#define Cc 256
#define Hh 128
#define Ww 128
#define Oo 256
#define HW 16384            // H*W
#define OFFC 72
#define NCH 36              // chunks: g*9 + tap, K=64 each
#define SROW 144            // S row stride bytes (64c*2B data + 16B pad)
#define SB2 (64 * SROW)     // S buffer bytes (9216)
#define XPW 129             // padded pair-row width
#define NQ 64               // channel quads per batch image
#define WFN (NCH * 8 * 4 * 2 * 32 * 4)   // u32 count of fragment-packed W

// Scratch (device globals: allocation-free rule)
__device__ float2 g_off2[Bb * 36 * HW];          // packed (dy,dx) per (b, g*9+tap, pixel)
__device__ uint32_t g_wf[WFN];                   // W pre-packed as mma B-fragments
__device__ uint4 g_xq[Bb * NQ * Hh * XPW];       // 4-channel quad of horizontal pairs per (y,xi)

// ---------------------------------------------------------------------------
// helpers
// ---------------------------------------------------------------------------
__device__ __forceinline__ uint32_t smem_u32(const void* p) {
    uint32_t a;
    asm("{ .reg .u64 t; cvta.to.shared.u64 t, %1; cvt.u32.u64 %0, t; }" : "=r"(a) : "l"(p));
    return a;
}
__device__ __forceinline__ void ldsm4(uint32_t* r, uint32_t addr) {
    asm volatile("ldmatrix.sync.aligned.m8n8.x4.shared.b16 {%0,%1,%2,%3}, [%4];"
                 : "=r"(r[0]), "=r"(r[1]), "=r"(r[2]), "=r"(r[3]) : "r"(addr));
}
__device__ __forceinline__ void mma_f16(float* c, const uint32_t* a, const uint32_t* b) {
    asm volatile(
        "mma.sync.aligned.m16n8k16.row.col.f32.f16.f16.f32 "
        "{%0,%1,%2,%3},{%4,%5,%6,%7},{%8,%9},{%0,%1,%2,%3};"
        : "+f"(c[0]), "+f"(c[1]), "+f"(c[2]), "+f"(c[3])
        : "r"(a[0]), "r"(a[1]), "r"(a[2]), "r"(a[3]), "r"(b[0]), "r"(b[1]));
}
__device__ __forceinline__ void sts128u(uint32_t a, uint32_t x, uint32_t y, uint32_t z, uint32_t w) {
    asm volatile("st.shared.v4.b32 [%0], {%1,%2,%3,%4};" :: "r"(a), "r"(x), "r"(y), "r"(z), "r"(w));
}
// f32x2 packed-FMA helpers (K1)
__device__ __forceinline__ void fma2(unsigned long long& d, unsigned long long a,
                                     unsigned long long b) {
    asm("fma.rn.f32x2 %0, %1, %2, %0;" : "+l"(d) : "l"(a), "l"(b));
}
__device__ __forceinline__ void unpack2(unsigned long long r, float& lo, float& hi) {
    asm("mov.b64 {%0, %1}, %2;" : "=f"(lo), "=f"(hi) : "l"(r));
}

// ---------------------------------------------------------------------------
// K0a: pack deform weights directly into m16n8k16 B-fragment layout (fp16).
// idx decomposition must match the k_deform load address:
//   idx = ((((cid*8 + wo)*4 + ks)*2 + g)*32 + lane)*4 + j4
// fragment: ni = g*2 + (j4>>1), reg rj = j4&1,
//   o = wo*32 + ni*8 + lane>>2,  k_lo = ks*16 + (lane&3)*2 + rj*8,
//   value = half2( W[o][c0][tap], W[o][c0+1][tap] ), c0 = (cid/9)*64 + k_lo.
// ---------------------------------------------------------------------------
__global__ void k_pack_wf(const float* __restrict__ w) {
    int idx = blockIdx.x * blockDim.x + threadIdx.x;
    if (idx >= WFN) return;
    int j4 = idx & 3;
    int l = (idx >> 2) & 31;
    int g = (idx >> 7) & 1;
    int ks = (idx >> 8) & 3;
    int wo = (idx >> 10) & 7;
    int cid = idx >> 13;
    int ni = g * 2 + (j4 >> 1);
    int rj = j4 & 1;
    int o = wo * 32 + ni * 8 + (l >> 2);
    int klo = ks * 16 + (l & 3) * 2 + rj * 8;
    int g4 = cid / 9;
    int tap = cid - g4 * 9;
    int c0 = g4 * 64 + klo;
    float f0 = __ldg(&w[((size_t)o * Cc + c0) * 9 + tap]);
    float f1 = __ldg(&w[((size_t)o * Cc + c0 + 1) * 9 + tap]);
    __half2 hh = __floats2half2_rn(f0, f1);
    g_wf[idx] = *(uint32_t*)&hh;
}

// ---------------------------------------------------------------------------
// K0b: pack x into 4-channel quads of fp16 horizontal pairs.
// ---------------------------------------------------------------------------
__global__ void k_pack_q(const float* __restrict__ x) {
    int idx = blockIdx.x * blockDim.x + threadIdx.x;
    if (idx >= Bb * NQ * Hh * XPW) return;
    int xi = idx % XPW;
    int rest = idx / XPW;         // (b*NQ+q)*Hh + y
    int y = rest & 127;
    int bq = rest >> 7;
    int q = bq & (NQ - 1);
    int b = bq >> 6;
    const float* src = x + ((size_t)(b * Cc + q * 4) * Hh + y) * Ww;
    uint32_t u[4];
#pragma unroll
    for (int j = 0; j < 4; ++j) {
        const float* s = src + (size_t)j * HW;
        float lo = (xi >= 1) ? __ldg(s + xi - 1) : 0.f;
        float hi = (xi <= 127) ? __ldg(s + xi) : 0.f;
        __half2 hh = __floats2half2_rn(lo, hi);
        u[j] = *(uint32_t*)&hh;
    }
    g_xq[idx] = make_uint4(u[0], u[1], u[2], u[3]);
}

// ---------------------------------------------------------------------------
// K1: offset field. 2 pixels/thread-team + o-split(2). (R9/R10 winner)
// ---------------------------------------------------------------------------
__global__ __launch_bounds__(256) void k_offset(const float* __restrict__ x,
                                                const float* __restrict__ w_off,
                                                const float* __restrict__ b_off) {
    extern __shared__ float ws[];  // [256][72], c-major
    for (int i = threadIdx.x; i < OFFC * Cc; i += blockDim.x) {
        int o = i / Cc, c = i % Cc;
        ws[c * OFFC + o] = w_off[i];
    }
    __syncthreads();

    const int team = threadIdx.x >> 1;
    const int oh = threadIdx.x & 1;
    int pix0 = blockIdx.x * 256 + team * 2;
    int b = pix0 >> 14;
    int hw = pix0 & (HW - 1);
    const float* xp = x + (size_t)b * Cc * HW + hw;

    unsigned long long acc[2][18];
#pragma unroll
    for (int i = 0; i < 18; i++) {
        unsigned long long bb = ((const unsigned long long*)b_off)[oh * 18 + i];
        acc[0][i] = bb;
        acc[1][i] = bb;
    }

    for (int c = 0; c < Cc; c++) {
        float2 v = __ldg((const float2*)&xp[(size_t)c * HW]);
        unsigned long long v0, v1;
        asm("mov.b64 %0, {%1, %1};" : "=l"(v0) : "f"(v.x));
        asm("mov.b64 %0, {%1, %1};" : "=l"(v1) : "f"(v.y));
        const float4* wrow = (const float4*)&ws[c * OFFC + oh * 36];
#pragma unroll
        for (int i = 0; i < 9; i++) {
            float4 w4 = wrow[i];
            unsigned long long w01, w23;
            asm("mov.b64 %0, {%1, %2};" : "=l"(w01) : "f"(w4.x), "f"(w4.y));
            asm("mov.b64 %0, {%1, %2};" : "=l"(w23) : "f"(w4.z), "f"(w4.w));
            fma2(acc[0][i * 2], v0, w01);
            fma2(acc[0][i * 2 + 1], v0, w23);
            fma2(acc[1][i * 2], v1, w01);
            fma2(acc[1][i * 2 + 1], v1, w23);
        }
    }
#pragma unroll
    for (int px = 0; px < 2; ++px) {
        float* op = (float*)(g_off2 + (size_t)b * 36 * HW);
#pragma unroll
        for (int i = 0; i < 18; i++) {
            float lo, hi;
            unpack2(acc[px][i], lo, hi);
            int q0 = oh * 36 + i * 2;
            int p0 = q0 >> 1;
            op[((size_t)p0 * HW + hw + px) * 2 + (q0 & 1)] = lo;
            int q1 = q0 + 1;
            int p1 = q1 >> 1;
            op[((size_t)p1 * HW + hw + px) * 2 + (q1 & 1)] = hi;
        }
    }
}

// ---------------------------------------------------------------------------
// K2: fused deformable conv + ReLU, fp16 mma.sync m16n8k16, fp32 accum.
// CTA = (b,h,pixel-half): 64p x 256o, 256 thr, 2 CTA/SM. 36 K-chunks of 64c.
// W comes STRAIGHT from global as pre-packed B fragments (LDG.128, L2-hot) —
// no smem for W at all. S double-buffered in smem (18KB total), one barrier
// per chunk. 8 warps: warp wo covers 64p x 32o (4 mi x 4 ni), A ldsm'd.
// ---------------------------------------------------------------------------
__global__ __launch_bounds__(256, 2) void k_deform(float* __restrict__ out) {
    extern __shared__ float dsm[];
    const uint32_t base = smem_u32(dsm);
    const uint32_t sSb[2] = {base, base + SB2};

    const int bx = blockIdx.x;
    const int pseg = bx & 1;
    const int h = (bx >> 1) & 127;
    const int b = bx >> 8;
    const int w0 = pseg * 64;
    const int tid = threadIdx.x;
    const int lid = tid & 31;
    const int wo = tid >> 5;       // o-slice (32o) of this warp

    // ldmatrix lane addressing (A)
    const uint32_t a_row16 = lid & 15;
    const uint32_t a_csel = lid >> 4;

    float acc[4][4][4];
#pragma unroll
    for (int i = 0; i < 4; i++)
#pragma unroll
        for (int j = 0; j < 4; j++)
#pragma unroll
            for (int k = 0; k < 4; k++) acc[i][j][k] = 0.f;

    const int sp = tid & 63;       // this thread's pixel within the 64-tile
    const int cq = tid >> 6;       // 0..3: which 16 channels of the 64-chunk
    const int wpix = w0 + sp;      // image column

    // --- sampler for chunk cid -> 8 packed half2 (16 channels, quad loads) ---
    auto sample = [&](int cid, uint32_t* v8) {
        const int g = cid / 9;
        const int tap = cid - g * 9;
        const float2 od = __ldg(&g_off2[((size_t)b * 36 + cid) * HW + h * Ww + wpix]);
        float ys = (float)(h - 1 + tap / 3) + od.x;
        float xs = (float)(wpix - 1 + tap % 3) + od.y;
        float y0f = floorf(ys), x0f = floorf(xs);
        float ly = ys - y0f, lx = xs - x0f;
        int y0 = (int)y0f;
        int xi = (int)x0f + 1;

        float wy0 = (y0 >= 0 && y0 < Hh) ? (1.f - ly) : 0.f;
        float wy1 = (y0 >= -1 && y0 < Hh - 1) ? ly : 0.f;
        bool okx = (xi >= 0 && xi <= Ww);
        float wl = okx ? (1.f - lx) : 0.f;
        float wh = okx ? lx : 0.f;
        int y0c = min(max(y0, 0), Hh - 1);
        int y1c = min(max(y0 + 1, 0), Hh - 1);
        int xic = min(max(xi, 0), Ww);

        const int qbase = (b * NQ + g * 16 + cq * 4);
#pragma unroll
        for (int jj = 0; jj < 4; ++jj) {
            const uint4* rowb = g_xq + (size_t)(qbase + jj) * (Hh * XPW);
            uint4 l0 = __ldg(rowb + y0c * XPW + xic);
            uint4 l1 = __ldg(rowb + y1c * XPW + xic);
            float s[4];
            const uint32_t* u0 = (const uint32_t*)&l0;
            const uint32_t* u1 = (const uint32_t*)&l1;
#pragma unroll
            for (int j = 0; j < 4; ++j) {
                float2 a = __half22float2(*(const __half2*)&u0[j]);
                float2 bb = __half22float2(*(const __half2*)&u1[j]);
                s[j] = (a.x * wl + a.y * wh) * wy0 + (bb.x * wl + bb.y * wh) * wy1;
            }
            __half2 h0 = __floats2half2_rn(s[0], s[1]);
            __half2 h1 = __floats2half2_rn(s[2], s[3]);
            v8[jj * 2] = *(uint32_t*)&h0;
            v8[jj * 2 + 1] = *(uint32_t*)&h1;
        }
    };

    // --- prologue: sample(0) ---
    uint32_t v8[8];
    sample(0, v8);

    const uint32_t s_addr = (uint32_t)(sp * SROW + cq * 32);
    const uint4* wf4 = (const uint4*)g_wf;

    for (int t = 0; t < NCH; ++t) {
        const int buf = t & 1;

        // --- B fragments for chunk t straight from global (L2-hot);
        //     issued before sts+barrier so latency hides under the sync ---
        uint4 bq[4][2];
        {
            const uint4* wp = wf4 + (size_t)(t * 8 + wo) * 8 + lid * 0; // base of this warp's chunk
            // element index: (((t*8+wo)*4+ks)*2+g)*32 + lid
#pragma unroll
            for (int ks = 0; ks < 4; ++ks)
#pragma unroll
                for (int g = 0; g < 2; ++g)
                    bq[ks][g] = __ldg(wf4 + ((size_t)((t * 8 + wo) * 4 + ks) * 2 + g) * 32 + lid);
            (void)wp;
        }

        sts128u(sSb[buf] + s_addr, v8[0], v8[1], v8[2], v8[3]);
        sts128u(sSb[buf] + s_addr + 16u, v8[4], v8[5], v8[6], v8[7]);
        __syncthreads();  // all warps' S(t) in place

        if (t + 1 < NCH)
            sample(t + 1, v8);   // LDG latency hides under gemm(t)

        // --- GEMM: acc[64p x 32o per warp] += S * W^T over 64 c ---
#pragma unroll
        for (int ks = 0; ks < 4; ++ks) {
            uint32_t afr[4][4];
#pragma unroll
            for (int mi = 0; mi < 4; ++mi) {
                uint32_t row = (uint32_t)(mi * 16) + a_row16;
                ldsm4(afr[mi], sSb[buf] + row * SROW + ((uint32_t)(ks * 2) + a_csel) * 16u);
            }
            const uint32_t* b0 = (const uint32_t*)&bq[ks][0];
            const uint32_t* b1 = (const uint32_t*)&bq[ks][1];
#pragma unroll
            for (int mi = 0; mi < 4; ++mi) {
                mma_f16(acc[mi][0], afr[mi], b0);
                mma_f16(acc[mi][1], afr[mi], b0 + 2);
                mma_f16(acc[mi][2], afr[mi], b1);
                mma_f16(acc[mi][3], afr[mi], b1 + 2);
            }
        }
    }

    // --- epilogue: ReLU + store ---
    {
        const int gq = lid >> 2;   // 0..7 (p within 16-tile)
        const int tq = lid & 3;    // 0..3 (o pairs)
#pragma unroll
        for (int mi = 0; mi < 4; ++mi) {
#pragma unroll
            for (int ni = 0; ni < 4; ++ni) {
                int o = wo * 32 + ni * 8 + 2 * tq;
                int p = w0 + mi * 16 + gq;
                float* op = out + ((size_t)(b * Oo + o)) * HW + h * Ww + p;
                op[0] = fmaxf(acc[mi][ni][0], 0.f);
                op[HW] = fmaxf(acc[mi][ni][1], 0.f);
                op[8] = fmaxf(acc[mi][ni][2], 0.f);
                op[HW + 8] = fmaxf(acc[mi][ni][3], 0.f);
            }
        }
    }
}

// ---------------------------------------------------------------------------
extern "C" void kernel_launch(void* const* d_in, const int* in_sizes, int n_in,
                              void* d_out, int out_size) {
    const float* x = (const float*)d_in[0];        // [2,256,128,128]
    const float* w_off = (const float*)d_in[1];    // [72,256,1,1]
    const float* b_off = (const float*)d_in[2];    // [72]
    const float* w_def = (const float*)d_in[3];    // [256,256,3,3]
    float* out = (float*)d_out;

    const int OFF_SMEM = OFFC * Cc * sizeof(float);   // 73728
    const int DEF_SMEM = 2 * SB2;                     // 18432

    cudaFuncSetAttribute(k_offset, cudaFuncAttributeMaxDynamicSharedMemorySize, OFF_SMEM);
    cudaFuncSetAttribute(k_deform, cudaFuncAttributeMaxDynamicSharedMemorySize, DEF_SMEM);

    k_pack_wf<<<(WFN + 255) / 256, 256>>>(w_def);
    k_pack_q<<<(Bb * NQ * Hh * XPW + 255) / 256, 256>>>(x);
    k_offset<<<(Bb * HW) / 256, 256, OFF_SMEM>>>(x, w_off, b_off);
    k_deform<<<Bb * Hh * 2, 256, DEF_SMEM>>>(out);
}

// round 12
// speedup vs baseline: 1.3408x; 1.0826x over previous
#include <cuda_runtime.h>
#include <cuda_fp16.h>
#include <cstdint>

// Problem constants
#define Bb 2
#define Cc 256
#define Hh 128
#define Ww 128
#define Oo 256
#define HW 16384            // H*W
#define OFFC 72
#define NCH2 18             // merged chunks: pair of flat (g,tap) indices, K=128
#define SROW 272            // S row stride bytes (128c*2B data + 16B pad)
#define SB2 (64 * SROW)     // S buffer bytes (17408)
#define XPW 129             // padded pair-row width
#define NQ 64               // channel quads per batch image
#define WFN (36 * 8 * 4 * 2 * 32 * 4)   // u32 count of fragment-packed W

// Scratch (device globals: allocation-free rule)
__device__ float2 g_off2[Bb * 36 * HW];          // packed (dy,dx) per (b, g*9+tap, pixel)
__device__ uint32_t g_wf[WFN];                   // W pre-packed as mma B-fragments
__device__ uint4 g_xq[Bb * NQ * Hh * XPW];       // 4-channel quad of horizontal pairs per (y,xi)

// ---------------------------------------------------------------------------
// helpers
// ---------------------------------------------------------------------------
__device__ __forceinline__ uint32_t smem_u32(const void* p) {
    uint32_t a;
    asm("{ .reg .u64 t; cvta.to.shared.u64 t, %1; cvt.u32.u64 %0, t; }" : "=r"(a) : "l"(p));
    return a;
}
__device__ __forceinline__ void ldsm4(uint32_t* r, uint32_t addr) {
    asm volatile("ldmatrix.sync.aligned.m8n8.x4.shared.b16 {%0,%1,%2,%3}, [%4];"
                 : "=r"(r[0]), "=r"(r[1]), "=r"(r[2]), "=r"(r[3]) : "r"(addr));
}
__device__ __forceinline__ void mma_f16(float* c, const uint32_t* a, const uint32_t* b) {
    asm volatile(
        "mma.sync.aligned.m16n8k16.row.col.f32.f16.f16.f32 "
        "{%0,%1,%2,%3},{%4,%5,%6,%7},{%8,%9},{%0,%1,%2,%3};"
        : "+f"(c[0]), "+f"(c[1]), "+f"(c[2]), "+f"(c[3])
        : "r"(a[0]), "r"(a[1]), "r"(a[2]), "r"(a[3]), "r"(b[0]), "r"(b[1]));
}
__device__ __forceinline__ void sts128u(uint32_t a, uint32_t x, uint32_t y, uint32_t z, uint32_t w) {
    asm volatile("st.shared.v4.b32 [%0], {%1,%2,%3,%4};" :: "r"(a), "r"(x), "r"(y), "r"(z), "r"(w));
}
// f32x2 packed-FMA helpers (K1)
__device__ __forceinline__ void fma2(unsigned long long& d, unsigned long long a,
                                     unsigned long long b) {
    asm("fma.rn.f32x2 %0, %1, %2, %0;" : "+l"(d) : "l"(a), "l"(b));
}
__device__ __forceinline__ void unpack2(unsigned long long r, float& lo, float& hi) {
    asm("mov.b64 {%0, %1}, %2;" : "=f"(lo), "=f"(hi) : "l"(r));
}

// ---------------------------------------------------------------------------
// K0a: pack deform weights into m16n8k16 B-fragment layout (fp16).
//   idx = ((((cid*8 + wo)*4 + ks)*2 + g)*32 + lane)*4 + j4      (cid = 0..35)
//   o = wo*32 + (g*2 + (j4>>1))*8 + lane>>2
//   k_lo = ks*16 + (lane&3)*2 + (j4&1)*8, c0 = (cid/9)*64 + k_lo, tap = cid%9
// ---------------------------------------------------------------------------
__global__ void k_pack_wf(const float* __restrict__ w) {
    int idx = blockIdx.x * blockDim.x + threadIdx.x;
    if (idx >= WFN) return;
    int j4 = idx & 3;
    int l = (idx >> 2) & 31;
    int g = (idx >> 7) & 1;
    int ks = (idx >> 8) & 3;
    int wo = (idx >> 10) & 7;
    int cid = idx >> 13;
    int ni = g * 2 + (j4 >> 1);
    int rj = j4 & 1;
    int o = wo * 32 + ni * 8 + (l >> 2);
    int klo = ks * 16 + (l & 3) * 2 + rj * 8;
    int g4 = cid / 9;
    int tap = cid - g4 * 9;
    int c0 = g4 * 64 + klo;
    float f0 = __ldg(&w[((size_t)o * Cc + c0) * 9 + tap]);
    float f1 = __ldg(&w[((size_t)o * Cc + c0 + 1) * 9 + tap]);
    __half2 hh = __floats2half2_rn(f0, f1);
    g_wf[idx] = *(uint32_t*)&hh;
}

// ---------------------------------------------------------------------------
// K0b: pack x into 4-channel quads of fp16 horizontal pairs.
// ---------------------------------------------------------------------------
__global__ void k_pack_q(const float* __restrict__ x) {
    int idx = blockIdx.x * blockDim.x + threadIdx.x;
    if (idx >= Bb * NQ * Hh * XPW) return;
    int xi = idx % XPW;
    int rest = idx / XPW;         // (b*NQ+q)*Hh + y
    int y = rest & 127;
    int bq = rest >> 7;
    int q = bq & (NQ - 1);
    int b = bq >> 6;
    const float* src = x + ((size_t)(b * Cc + q * 4) * Hh + y) * Ww;
    uint32_t u[4];
#pragma unroll
    for (int j = 0; j < 4; ++j) {
        const float* s = src + (size_t)j * HW;
        float lo = (xi >= 1) ? __ldg(s + xi - 1) : 0.f;
        float hi = (xi <= 127) ? __ldg(s + xi) : 0.f;
        __half2 hh = __floats2half2_rn(lo, hi);
        u[j] = *(uint32_t*)&hh;
    }
    g_xq[idx] = make_uint4(u[0], u[1], u[2], u[3]);
}

// ---------------------------------------------------------------------------
// K1: offset field. 2 pixels/thread-team + o-split(2). (unchanged winner)
// ---------------------------------------------------------------------------
__global__ __launch_bounds__(256) void k_offset(const float* __restrict__ x,
                                                const float* __restrict__ w_off,
                                                const float* __restrict__ b_off) {
    extern __shared__ float ws[];  // [256][72], c-major
    for (int i = threadIdx.x; i < OFFC * Cc; i += blockDim.x) {
        int o = i / Cc, c = i % Cc;
        ws[c * OFFC + o] = w_off[i];
    }
    __syncthreads();

    const int team = threadIdx.x >> 1;
    const int oh = threadIdx.x & 1;
    int pix0 = blockIdx.x * 256 + team * 2;
    int b = pix0 >> 14;
    int hw = pix0 & (HW - 1);
    const float* xp = x + (size_t)b * Cc * HW + hw;

    unsigned long long acc[2][18];
#pragma unroll
    for (int i = 0; i < 18; i++) {
        unsigned long long bb = ((const unsigned long long*)b_off)[oh * 18 + i];
        acc[0][i] = bb;
        acc[1][i] = bb;
    }

    for (int c = 0; c < Cc; c++) {
        float2 v = __ldg((const float2*)&xp[(size_t)c * HW]);
        unsigned long long v0, v1;
        asm("mov.b64 %0, {%1, %1};" : "=l"(v0) : "f"(v.x));
        asm("mov.b64 %0, {%1, %1};" : "=l"(v1) : "f"(v.y));
        const float4* wrow = (const float4*)&ws[c * OFFC + oh * 36];
#pragma unroll
        for (int i = 0; i < 9; i++) {
            float4 w4 = wrow[i];
            unsigned long long w01, w23;
            asm("mov.b64 %0, {%1, %2};" : "=l"(w01) : "f"(w4.x), "f"(w4.y));
            asm("mov.b64 %0, {%1, %2};" : "=l"(w23) : "f"(w4.z), "f"(w4.w));
            fma2(acc[0][i * 2], v0, w01);
            fma2(acc[0][i * 2 + 1], v0, w23);
            fma2(acc[1][i * 2], v1, w01);
            fma2(acc[1][i * 2 + 1], v1, w23);
        }
    }
#pragma unroll
    for (int px = 0; px < 2; ++px) {
        float* op = (float*)(g_off2 + (size_t)b * 36 * HW);
#pragma unroll
        for (int i = 0; i < 18; i++) {
            float lo, hi;
            unpack2(acc[px][i], lo, hi);
            int q0 = oh * 36 + i * 2;
            int p0 = q0 >> 1;
            op[((size_t)p0 * HW + hw + px) * 2 + (q0 & 1)] = lo;
            int q1 = q0 + 1;
            int p1 = q1 >> 1;
            op[((size_t)p1 * HW + hw + px) * 2 + (q1 & 1)] = hi;
        }
    }
}

// ---------------------------------------------------------------------------
// K2: fused deformable conv + ReLU, fp16 mma.sync m16n8k16, fp32 accum.
// CTA = (b,h,pixel-half): 64p x 256o, 256 thr, 2 CTA/SM.
// 18 merged K-chunks of 128c (two flat (g,tap) subs): HALF the barriers,
// 2x longer gemm phases to hide gather + W-fragment latency.
// W fragments straight from global (L2-hot), register double-buffered per ks.
// S double-buffered (2x17KB). 8 warps: warp wo = 64p x 32o.
// ---------------------------------------------------------------------------
__global__ __launch_bounds__(256, 2) void k_deform(float* __restrict__ out) {
    extern __shared__ float dsm[];
    const uint32_t base = smem_u32(dsm);
    const uint32_t sSb[2] = {base, base + SB2};

    const int bx = blockIdx.x;
    const int pseg = bx & 1;
    const int h = (bx >> 1) & 127;
    const int b = bx >> 8;
    const int w0 = pseg * 64;
    const int tid = threadIdx.x;
    const int lid = tid & 31;
    const int wo = tid >> 5;       // o-slice (32o) of this warp

    // ldmatrix lane addressing (A)
    const uint32_t a_row16 = lid & 15;
    const uint32_t a_csel = lid >> 4;

    float acc[4][4][4];
#pragma unroll
    for (int i = 0; i < 4; i++)
#pragma unroll
        for (int j = 0; j < 4; j++)
#pragma unroll
            for (int k = 0; k < 4; k++) acc[i][j][k] = 0.f;

    const int sp = tid & 63;       // this thread's pixel within the 64-tile
    const int cq = tid >> 6;       // 0..3: which 16 channels of each 64c sub
    const int wpix = w0 + sp;      // image column

    // --- sampler for flat (g,tap) index f -> 8 packed half2 (16 channels) ---
    auto sample = [&](int f, uint32_t* v8) {
        const int g = f / 9;
        const int tap = f - g * 9;
        const float2 od = __ldg(&g_off2[((size_t)b * 36 + f) * HW + h * Ww + wpix]);
        float ys = (float)(h - 1 + tap / 3) + od.x;
        float xs = (float)(wpix - 1 + tap % 3) + od.y;
        float y0f = floorf(ys), x0f = floorf(xs);
        float ly = ys - y0f, lx = xs - x0f;
        int y0 = (int)y0f;
        int xi = (int)x0f + 1;

        float wy0 = (y0 >= 0 && y0 < Hh) ? (1.f - ly) : 0.f;
        float wy1 = (y0 >= -1 && y0 < Hh - 1) ? ly : 0.f;
        bool okx = (xi >= 0 && xi <= Ww);
        float wl = okx ? (1.f - lx) : 0.f;
        float wh = okx ? lx : 0.f;
        int y0c = min(max(y0, 0), Hh - 1);
        int y1c = min(max(y0 + 1, 0), Hh - 1);
        int xic = min(max(xi, 0), Ww);

        const int qbase = (b * NQ + g * 16 + cq * 4);
#pragma unroll
        for (int jj = 0; jj < 4; ++jj) {
            const uint4* rowb = g_xq + (size_t)(qbase + jj) * (Hh * XPW);
            uint4 l0 = __ldg(rowb + y0c * XPW + xic);
            uint4 l1 = __ldg(rowb + y1c * XPW + xic);
            float s[4];
            const uint32_t* u0 = (const uint32_t*)&l0;
            const uint32_t* u1 = (const uint32_t*)&l1;
#pragma unroll
            for (int j = 0; j < 4; ++j) {
                float2 a = __half22float2(*(const __half2*)&u0[j]);
                float2 bb = __half22float2(*(const __half2*)&u1[j]);
                s[j] = (a.x * wl + a.y * wh) * wy0 + (bb.x * wl + bb.y * wh) * wy1;
            }
            __half2 h0 = __floats2half2_rn(s[0], s[1]);
            __half2 h1 = __floats2half2_rn(s[2], s[3]);
            v8[jj * 2] = *(uint32_t*)&h0;
            v8[jj * 2 + 1] = *(uint32_t*)&h1;
        }
    };

    const uint4* wf4 = (const uint4*)g_wf;
    // B-fragment loader: merged chunk t, k-step ks (0..7) -> 2 uint4
    auto load_bq = [&](int t, int ks, uint4* dst) {
        int cidf = 2 * t + (ks >> 2);
        int ko = ks & 3;
#pragma unroll
        for (int g = 0; g < 2; ++g)
            dst[g] = __ldg(wf4 + ((size_t)((cidf * 8 + wo) * 4 + ko) * 2 + g) * 32 + lid);
    };

    // --- prologue: sample both subs of chunk 0 ---
    uint32_t v16[16];
    sample(0, v16);
    sample(1, v16 + 8);

    const uint32_t s_addr0 = (uint32_t)(sp * SROW + cq * 32);          // sub0
    const uint32_t s_addr1 = (uint32_t)(sp * SROW + 128 + cq * 32);    // sub1

    for (int t = 0; t < NCH2; ++t) {
        const int buf = t & 1;

        uint4 bq[2][2];
        load_bq(t, 0, bq[0]);    // ks=0 fragments hide under sts+barrier

        sts128u(sSb[buf] + s_addr0, v16[0], v16[1], v16[2], v16[3]);
        sts128u(sSb[buf] + s_addr0 + 16u, v16[4], v16[5], v16[6], v16[7]);
        sts128u(sSb[buf] + s_addr1, v16[8], v16[9], v16[10], v16[11]);
        sts128u(sSb[buf] + s_addr1 + 16u, v16[12], v16[13], v16[14], v16[15]);
        __syncthreads();  // all warps' S(t) in place; gemm(t-1) done

        if (t + 1 < NCH2) {      // gather latency hides under gemm(t)
            sample(2 * t + 2, v16);
            sample(2 * t + 3, v16 + 8);
        }

        // --- GEMM: acc[64p x 32o per warp] += S * W^T over 128 c ---
#pragma unroll
        for (int ks = 0; ks < 8; ++ks) {
            if (ks + 1 < 8) load_bq(t, ks + 1, bq[(ks + 1) & 1]);
            const uint32_t coff = (uint32_t)((ks >> 2) * 128 + ((ks & 3) * 2 + a_csel) * 16);
            uint32_t afr[4][4];
#pragma unroll
            for (int mi = 0; mi < 4; ++mi) {
                uint32_t row = (uint32_t)(mi * 16) + a_row16;
                ldsm4(afr[mi], sSb[buf] + row * SROW + coff);
            }
            const uint32_t* b0 = (const uint32_t*)&bq[ks & 1][0];
            const uint32_t* b1 = (const uint32_t*)&bq[ks & 1][1];
#pragma unroll
            for (int mi = 0; mi < 4; ++mi) {
                mma_f16(acc[mi][0], afr[mi], b0);
                mma_f16(acc[mi][1], afr[mi], b0 + 2);
                mma_f16(acc[mi][2], afr[mi], b1);
                mma_f16(acc[mi][3], afr[mi], b1 + 2);
            }
        }
    }

    // --- epilogue: ReLU + store ---
    {
        const int gq = lid >> 2;   // 0..7 (p within 16-tile)
        const int tq = lid & 3;    // 0..3 (o pairs)
#pragma unroll
        for (int mi = 0; mi < 4; ++mi) {
#pragma unroll
            for (int ni = 0; ni < 4; ++ni) {
                int o = wo * 32 + ni * 8 + 2 * tq;
                int p = w0 + mi * 16 + gq;
                float* op = out + ((size_t)(b * Oo + o)) * HW + h * Ww + p;
                op[0] = fmaxf(acc[mi][ni][0], 0.f);
                op[HW] = fmaxf(acc[mi][ni][1], 0.f);
                op[8] = fmaxf(acc[mi][ni][2], 0.f);
                op[HW + 8] = fmaxf(acc[mi][ni][3], 0.f);
            }
        }
    }
}

// ---------------------------------------------------------------------------
extern "C" void kernel_launch(void* const* d_in, const int* in_sizes, int n_in,
                              void* d_out, int out_size) {
    const float* x = (const float*)d_in[0];        // [2,256,128,128]
    const float* w_off = (const float*)d_in[1];    // [72,256,1,1]
    const float* b_off = (const float*)d_in[2];    // [72]
    const float* w_def = (const float*)d_in[3];    // [256,256,3,3]
    float* out = (float*)d_out;

    const int OFF_SMEM = OFFC * Cc * sizeof(float);   // 73728
    const int DEF_SMEM = 2 * SB2;                     // 34816

    cudaFuncSetAttribute(k_offset, cudaFuncAttributeMaxDynamicSharedMemorySize, OFF_SMEM);
    cudaFuncSetAttribute(k_deform, cudaFuncAttributeMaxDynamicSharedMemorySize, DEF_SMEM);

    k_pack_wf<<<(WFN + 255) / 256, 256>>>(w_def);
    k_pack_q<<<(Bb * NQ * Hh * XPW + 255) / 256, 256>>>(x);
    k_offset<<<(Bb * HW) / 256, 256, OFF_SMEM>>>(x, w_off, b_off);
    k_deform<<<Bb * Hh * 2, 256, DEF_SMEM>>>(out);
}